// round 15
// baseline (speedup 1.0000x reference)
#include <cuda_runtime.h>
#include <cuda_bf16.h>
#include <cstdint>

// Problem constants
#define Bv   16
#define Nv   4096
#define Mv   1024
#define C1v  256
#define C2v  512
#define Hv   256
#define NPTS  (Bv * Nv)    // 65536
#define KFROWS (Bv * Mv)   // 16384

// ---------------- device-global scratch (no cudaMalloc allowed) -------------
static __device__ __nv_bfloat16 g_kf_hi[(size_t)KFROWS * C2v], g_kf_lo[(size_t)KFROWS * C2v];
static __device__ __nv_bfloat16 g_uf_hi[(size_t)NPTS * C1v],   g_uf_lo[(size_t)NPTS * C1v];
static __device__ __nv_bfloat16 g_w1a_hi[Hv * C1v], g_w1a_lo[Hv * C1v];
static __device__ __nv_bfloat16 g_w1b_hi[Hv * C2v], g_w1b_lo[Hv * C2v];
static __device__ __nv_bfloat16 g_w2_hi[Hv * Hv],   g_w2_lo[Hv * Hv];
static __device__ float g_kfW[(size_t)KFROWS * Hv];
static __device__ float g_y1[(size_t)NPTS * Hv];
static __device__ float g_y2[(size_t)NPTS * Hv];
static __device__ int4   g_nni[NPTS];
static __device__ float4 g_nnw[NPTS];
static __device__ float g_psum[256 * Hv], g_psq[256 * Hv];
static __device__ float g_sc1[Hv], g_sh1[Hv], g_sc2[Hv], g_sh2[Hv];

// ---------------- PTX helpers (baseline sm_80+, no 'a' features) ------------
__device__ __forceinline__ uint32_t smem_u32(const void* p) {
    uint32_t a;
    asm("{ .reg .u64 t; cvta.to.shared.u64 t, %1; cvt.u32.u64 %0, t; }" : "=r"(a) : "l"(p));
    return a;
}
__device__ __forceinline__ void cpasync16(uint32_t dst, const void* src) {
    size_t g = __cvta_generic_to_global(src);
    asm volatile("cp.async.cg.shared.global [%0], [%1], 16;" :: "r"(dst), "l"(g));
}
#define CP_COMMIT() asm volatile("cp.async.commit_group;" ::: "memory")
#define CP_WAIT0()  asm volatile("cp.async.wait_group 0;" ::: "memory")

__device__ __forceinline__ void ldsm4(uint32_t* r, uint32_t addr) {
    asm volatile("ldmatrix.sync.aligned.m8n8.x4.shared.b16 {%0,%1,%2,%3}, [%4];"
        : "=r"(r[0]), "=r"(r[1]), "=r"(r[2]), "=r"(r[3]) : "r"(addr));
}
__device__ __forceinline__ void mma16816(float* d, const uint32_t* a, const uint32_t* b) {
    asm volatile(
        "mma.sync.aligned.m16n8k16.row.col.f32.bf16.bf16.f32 "
        "{%0,%1,%2,%3}, {%4,%5,%6,%7}, {%8,%9}, {%0,%1,%2,%3};"
        : "+f"(d[0]), "+f"(d[1]), "+f"(d[2]), "+f"(d[3])
        : "r"(a[0]), "r"(a[1]), "r"(a[2]), "r"(a[3]), "r"(b[0]), "r"(b[1]));
}

// ---------------- bf16 split helpers ----------------------------------------
__device__ __forceinline__ void split_bf16(float v, __nv_bfloat16& h, __nv_bfloat16& l) {
    h = __float2bfloat16(v);
    l = __float2bfloat16(v - __bfloat162float(h));
}
__device__ __forceinline__ uint32_t pack2(__nv_bfloat16 a, __nv_bfloat16 b) {
    __nv_bfloat162 t(a, b);
    return *reinterpret_cast<uint32_t*>(&t);
}

// ---------------- weight split (w is already [N,K] K-major) -----------------
__global__ void conv_w1(const float* __restrict__ w1) {
    int i = blockIdx.x * 256 + threadIdx.x;   // 256*768
    int n = i / 768, k = i % 768;
    __nv_bfloat16 h, l;
    split_bf16(w1[i], h, l);
    if (k < C1v) { g_w1a_hi[n * C1v + k] = h; g_w1a_lo[n * C1v + k] = l; }
    else { g_w1b_hi[n * C2v + k - C1v] = h; g_w1b_lo[n * C2v + k - C1v] = l; }
}
__global__ void conv_w2(const float* __restrict__ w2) {
    int i = blockIdx.x * 256 + threadIdx.x;
    __nv_bfloat16 h, l;
    split_bf16(w2[i], h, l);
    g_w2_hi[i] = h; g_w2_lo[i] = l;
}

// ---------------- transpose + split: (B, C, Nper) -> (B*Nper, C) hi/lo ------
template <int WHICH>   // 0: kf (C=512, Nper=1024)  1: uf (C=256, Nper=4096)
__global__ void conv_transpose(const float* __restrict__ in) {
    constexpr int C = (WHICH == 0) ? C2v : C1v;
    constexpr int Nper = (WHICH == 0) ? Mv : Nv;
    __nv_bfloat16* hi = (WHICH == 0) ? g_kf_hi : g_uf_hi;
    __nv_bfloat16* lo = (WHICH == 0) ? g_kf_lo : g_uf_lo;
    __shared__ float t[32][33];
    const int b = blockIdx.z;
    const int n0 = blockIdx.x * 32, c0 = blockIdx.y * 32;
    const float* ib = in + ((size_t)b * C + c0) * Nper + n0;
#pragma unroll
    for (int i = threadIdx.y; i < 32; i += 8)
        t[i][threadIdx.x] = ib[(size_t)i * Nper + threadIdx.x];
    __syncthreads();
    size_t base = ((size_t)b * Nper + n0) * C + c0 + threadIdx.x;
#pragma unroll
    for (int i = threadIdx.y; i < 32; i += 8) {
        __nv_bfloat16 h, l;
        split_bf16(t[threadIdx.x][i], h, l);
        hi[base + (size_t)i * C] = h;
        lo[base + (size_t)i * C] = l;
    }
}

// ---------------- 3-NN ------------------------------------------------------
__global__ __launch_bounds__(256) void knn_kernel(
    const float* __restrict__ unknown, const float* __restrict__ known) {
    __shared__ float4 kn[Mv];
    const int b = blockIdx.x;
    const int tid = threadIdx.x;
    const float* kb = known + (long)b * Mv * 3;
    for (int m = tid; m < Mv; m += 256) {
        float x = kb[m * 3], y = kb[m * 3 + 1], z = kb[m * 3 + 2];
        kn[m] = make_float4(x, y, z, x * x + y * y + z * z);
    }
    __syncthreads();
    const int n = blockIdx.y * 256 + tid;
    const float* up = unknown + ((long)b * Nv + n) * 3;
    float ux = up[0], uy = up[1], uz = up[2];
    float un2 = ux * ux + uy * uy + uz * uz;
    float ax = -2.f * ux, ay = -2.f * uy, az = -2.f * uz;
    float d0 = 1e30f, d1 = 1e30f, d2 = 1e30f;
    int i0 = 0, i1 = 0, i2 = 0;
#pragma unroll 4
    for (int m = 0; m < Mv; m++) {
        float4 p = kn[m];
        float d = fmaf(ax, p.x, fmaf(ay, p.y, fmaf(az, p.z, p.w)));
        if (d < d2) {
            if (d < d1) {
                d2 = d1; i2 = i1;
                if (d < d0) { d1 = d0; i1 = i0; d0 = d; i0 = m; }
                else        { d1 = d;  i1 = m; }
            } else { d2 = d; i2 = m; }
        }
    }
    d0 += un2; d1 += un2; d2 += un2;
    float w0 = 1.f / (d0 + 1e-8f), w1 = 1.f / (d1 + 1e-8f), w2 = 1.f / (d2 + 1e-8f);
    float ws = 1.f / (w0 + w1 + w2);
    g_nni[(long)b * Nv + n] = make_int4(i0, i1, i2, 0);
    g_nnw[(long)b * Nv + n] = make_float4(w0 * ws, w1 * ws, w2 * ws, 0.f);
}

// ---------------- pipelined HMMA bf16x3 GEMM (MODE 0/1), 2-stage -------------
// MODE 0: kfW = kf @ w1b^T   (K=512)
// MODE 1: y1  = uf @ w1a^T + NN-gather epilogue (K=256)
// SMEM per stage (64KB): A_HI +0, A_LO +16K, B_HI +32K, B_LO +48K; 2 stages.
template <int MODE>
__global__ __launch_bounds__(256, 1) void mma_gemm_pipe() {
    constexpr int KTOT = (MODE == 0) ? C2v : Hv;
    constexpr int NCH = KTOT / 64;
    constexpr uint32_t A_HI = 0, A_LO = 16384, B_HI = 32768, B_LO = 49152;
    constexpr uint32_t STAGE = 65536;

    extern __shared__ char smem[];
    const uint32_t sb = smem_u32(smem);

    const __nv_bfloat16* Ahi = (MODE == 0) ? g_kf_hi : g_uf_hi;
    const __nv_bfloat16* Alo = (MODE == 0) ? g_kf_lo : g_uf_lo;
    const __nv_bfloat16* Bhi = (MODE == 0) ? g_w1b_hi : g_w1a_hi;
    const __nv_bfloat16* Blo = (MODE == 0) ? g_w1b_lo : g_w1a_lo;
    float* Cout = (MODE == 0) ? g_kfW : g_y1;

    const int tid = threadIdx.x;
    const int lane = tid & 31, wid = tid >> 5;
    const int wr = wid & 3, wc = wid >> 2;        // warp grid 4(m) x 2(n)
    const long m0 = (long)blockIdx.x * 128;
    const int n0g = blockIdx.y * 128;

    float acc[2][8][4];
#pragma unroll
    for (int i = 0; i < 2; i++)
#pragma unroll
        for (int j = 0; j < 8; j++)
#pragma unroll
            for (int k = 0; k < 4; k++) acc[i][j][k] = 0.f;

    const int a_r = lane & 15;
    const int a_co = lane >> 4;
    const int b_r = (lane & 7) + ((lane >> 4) << 3);
    const int b_co = (lane >> 3) & 1;

    // loader thread mapping
    const int lr = tid >> 3, lc = tid & 7;
    const uint32_t lsw = lr * 128 + (((uint32_t)(lc ^ (lr & 7))) << 4);

    // ---- prologue: load chunk 0 into stage 0 ----
    {
        const int k0 = 0;
#pragma unroll
        for (int p = 0; p < 4; p++) {
            int r = lr + p * 32;
            uint32_t sw = lsw + p * 32 * 128;
            const size_t gia = (m0 + r) * (size_t)KTOT + k0 + lc * 8;
            cpasync16(sb + A_HI + sw, Ahi + gia);
            cpasync16(sb + A_LO + sw, Alo + gia);
            const size_t gib = (size_t)(n0g + r) * KTOT + k0 + lc * 8;
            cpasync16(sb + B_HI + sw, Bhi + gib);
            cpasync16(sb + B_LO + sw, Blo + gib);
        }
        CP_COMMIT();
    }

#pragma unroll 1
    for (int kc = 0; kc < NCH; kc++) {
        const uint32_t st = (kc & 1) * STAGE;
        CP_WAIT0();
        __syncthreads();
        // issue next chunk's loads into the other stage (overlaps compute below)
        if (kc + 1 < NCH) {
            const int k0 = (kc + 1) * 64;
            const uint32_t so = ((kc + 1) & 1) * STAGE;
#pragma unroll
            for (int p = 0; p < 4; p++) {
                int r = lr + p * 32;
                uint32_t sw = lsw + p * 32 * 128;
                const size_t gia = (m0 + r) * (size_t)KTOT + k0 + lc * 8;
                cpasync16(sb + so + A_HI + sw, Ahi + gia);
                cpasync16(sb + so + A_LO + sw, Alo + gia);
                const size_t gib = (size_t)(n0g + r) * KTOT + k0 + lc * 8;
                cpasync16(sb + so + B_HI + sw, Bhi + gib);
                cpasync16(sb + so + B_LO + sw, Blo + gib);
            }
            CP_COMMIT();
        }

        // ---- compute 4 k16 steps on stage st ----
#pragma unroll 1
        for (int kk = 0; kk < 4; kk++) {
            uint32_t ah[2][4], al[2][4];
#pragma unroll
            for (int mt = 0; mt < 2; mt++) {
                int row = wr * 32 + mt * 16 + a_r;
                uint32_t ac = (uint32_t)((2 * kk + a_co) ^ (row & 7));
                uint32_t ad = sb + st + A_HI + row * 128 + (ac << 4);
                ldsm4(ah[mt], ad);
                ldsm4(al[mt], ad + (A_LO - A_HI));
            }
#pragma unroll
            for (int nt2 = 0; nt2 < 4; nt2++) {
                int row = wc * 64 + nt2 * 16 + b_r;
                uint32_t bc = (uint32_t)((2 * kk + b_co) ^ (row & 7));
                uint32_t bd = sb + st + B_HI + row * 128 + (bc << 4);
                uint32_t bh[4], bl[4];
                ldsm4(bh, bd);
                ldsm4(bl, bd + (B_LO - B_HI));
#pragma unroll
                for (int mt = 0; mt < 2; mt++) {
                    mma16816(acc[mt][nt2 * 2 + 0], ah[mt], bh + 0);
                    mma16816(acc[mt][nt2 * 2 + 0], ah[mt], bl + 0);
                    mma16816(acc[mt][nt2 * 2 + 0], al[mt], bh + 0);
                    mma16816(acc[mt][nt2 * 2 + 1], ah[mt], bh + 2);
                    mma16816(acc[mt][nt2 * 2 + 1], ah[mt], bl + 2);
                    mma16816(acc[mt][nt2 * 2 + 1], al[mt], bh + 2);
                }
            }
        }
    }
    __syncthreads();

    // ---- epilogue ----
    int4* sidx = (int4*)smem;
    float4* swt = (float4*)(smem + 2048);
    int bIdx = 0;
    if (MODE == 1) {
        bIdx = (int)(m0 >> 12);
        if (tid < 128) {
            sidx[tid] = g_nni[m0 + tid];
            swt[tid] = g_nnw[m0 + tid];
        }
        __syncthreads();
    }
    const float* kfb = g_kfW + (size_t)bIdx * Mv * Hv;
    const int g = lane >> 2, tg = lane & 3;
#pragma unroll
    for (int mt = 0; mt < 2; mt++) {
#pragma unroll
        for (int h = 0; h < 2; h++) {
            int rl = wr * 32 + mt * 16 + h * 8 + g;
            long grow = m0 + rl;
            int4 id;
            float4 w;
            if (MODE == 1) { id = sidx[rl]; w = swt[rl]; }
            float* crow = Cout + grow * Hv + n0g + wc * 64 + tg * 2;
#pragma unroll
            for (int nt = 0; nt < 8; nt++) {
                float2 v = {acc[mt][nt][2 * h], acc[mt][nt][2 * h + 1]};
                if (MODE == 1) {
                    int col = n0g + wc * 64 + nt * 8 + tg * 2;
                    float2 f0 = *(const float2*)(kfb + (size_t)id.x * Hv + col);
                    float2 f1 = *(const float2*)(kfb + (size_t)id.y * Hv + col);
                    float2 f2 = *(const float2*)(kfb + (size_t)id.z * Hv + col);
                    v.x += w.x * f0.x + w.y * f1.x + w.z * f2.x;
                    v.y += w.x * f0.y + w.y * f1.y + w.z * f2.y;
                }
                *(float2*)(crow + nt * 8) = v;
            }
        }
    }
}

// ---------------- GEMM2 (R6-exact): y2 = relu(bn1(y1)) @ w2^T ----------------
__global__ __launch_bounds__(256, 2) void mma_gemm_bn() {
    constexpr int KTOT = Hv;
    constexpr int NCH = KTOT / 64;
    constexpr uint32_t A_HI = 0, A_LO = 16384, B_HI = 32768, B_LO = 49152;

    extern __shared__ char smem[];
    const uint32_t sb = smem_u32(smem);

    const __nv_bfloat16* Bhi = g_w2_hi;
    const __nv_bfloat16* Blo = g_w2_lo;
    float* Cout = g_y2;

    const int tid = threadIdx.x;
    const int lane = tid & 31, wid = tid >> 5;
    const int wr = wid & 3, wc = wid >> 2;
    const long m0 = (long)blockIdx.x * 128;
    const int n0g = blockIdx.y * 128;

    float* s_sc = (float*)(smem + 65536);
    float* s_sh = (float*)(smem + 65536 + 1024);
    if (tid < 64) {
        ((float4*)s_sc)[tid] = ((const float4*)g_sc1)[tid];
        ((float4*)s_sh)[tid] = ((const float4*)g_sh1)[tid];
    }
    __syncthreads();

    float acc[2][8][4];
#pragma unroll
    for (int i = 0; i < 2; i++)
#pragma unroll
        for (int j = 0; j < 8; j++)
#pragma unroll
            for (int k = 0; k < 4; k++) acc[i][j][k] = 0.f;

    const int a_r = lane & 15;
    const int a_co = lane >> 4;
    const int b_r = (lane & 7) + ((lane >> 4) << 3);
    const int b_co = (lane >> 3) & 1;

#pragma unroll 1
    for (int kc = 0; kc < NCH; kc++) {
        const int k0 = kc * 64;
        // A: BN+ReLU+split synchronous
#pragma unroll
        for (int p = 0; p < 4; p++) {
            int idx = p * 256 + tid;
            int r = idx >> 3, c = idx & 7;
            int kb = k0 + c * 8;
            const float* src = g_y1 + (m0 + r) * (size_t)Hv + kb;
            float4 x0 = *(const float4*)src;
            float4 x1 = *(const float4*)(src + 4);
            float v[8];
            v[0] = fmaxf(fmaf(x0.x, s_sc[kb + 0], s_sh[kb + 0]), 0.f);
            v[1] = fmaxf(fmaf(x0.y, s_sc[kb + 1], s_sh[kb + 1]), 0.f);
            v[2] = fmaxf(fmaf(x0.z, s_sc[kb + 2], s_sh[kb + 2]), 0.f);
            v[3] = fmaxf(fmaf(x0.w, s_sc[kb + 3], s_sh[kb + 3]), 0.f);
            v[4] = fmaxf(fmaf(x1.x, s_sc[kb + 4], s_sh[kb + 4]), 0.f);
            v[5] = fmaxf(fmaf(x1.y, s_sc[kb + 5], s_sh[kb + 5]), 0.f);
            v[6] = fmaxf(fmaf(x1.z, s_sc[kb + 6], s_sh[kb + 6]), 0.f);
            v[7] = fmaxf(fmaf(x1.w, s_sc[kb + 7], s_sh[kb + 7]), 0.f);
            uint4 hq, lq;
            uint32_t* hp = (uint32_t*)&hq;
            uint32_t* lp = (uint32_t*)&lq;
#pragma unroll
            for (int j = 0; j < 4; j++) {
                __nv_bfloat16 h0, l0, h1, l1;
                split_bf16(v[2 * j], h0, l0);
                split_bf16(v[2 * j + 1], h1, l1);
                hp[j] = pack2(h0, h1);
                lp[j] = pack2(l0, l1);
            }
            uint32_t sw = r * 128 + (((uint32_t)(c ^ (r & 7))) << 4);
            *(uint4*)(smem + A_HI + sw) = hq;
            *(uint4*)(smem + A_LO + sw) = lq;
        }
        // B: async
#pragma unroll
        for (int p = 0; p < 4; p++) {
            int idx = p * 256 + tid;
            int r = idx >> 3, c = idx & 7;
            uint32_t sw = r * 128 + (((uint32_t)(c ^ (r & 7))) << 4);
            const size_t gi = (size_t)(n0g + r) * KTOT + k0 + c * 8;
            cpasync16(sb + B_HI + sw, Bhi + gi);
            cpasync16(sb + B_LO + sw, Blo + gi);
        }
        CP_COMMIT();
        CP_WAIT0();
        __syncthreads();

#pragma unroll 1
        for (int kk = 0; kk < 4; kk++) {
            uint32_t ah[2][4], al[2][4];
#pragma unroll
            for (int mt = 0; mt < 2; mt++) {
                int row = wr * 32 + mt * 16 + a_r;
                uint32_t ac = (uint32_t)((2 * kk + a_co) ^ (row & 7));
                uint32_t ad = sb + A_HI + row * 128 + (ac << 4);
                ldsm4(ah[mt], ad);
                ldsm4(al[mt], ad + (A_LO - A_HI));
            }
#pragma unroll
            for (int nt2 = 0; nt2 < 4; nt2++) {
                int row = wc * 64 + nt2 * 16 + b_r;
                uint32_t bc = (uint32_t)((2 * kk + b_co) ^ (row & 7));
                uint32_t bd = sb + B_HI + row * 128 + (bc << 4);
                uint32_t bh[4], bl[4];
                ldsm4(bh, bd);
                ldsm4(bl, bd + (B_LO - B_HI));
#pragma unroll
                for (int mt = 0; mt < 2; mt++) {
                    mma16816(acc[mt][nt2 * 2 + 0], ah[mt], bh + 0);
                    mma16816(acc[mt][nt2 * 2 + 0], ah[mt], bl + 0);
                    mma16816(acc[mt][nt2 * 2 + 0], al[mt], bh + 0);
                    mma16816(acc[mt][nt2 * 2 + 1], ah[mt], bh + 2);
                    mma16816(acc[mt][nt2 * 2 + 1], ah[mt], bl + 2);
                    mma16816(acc[mt][nt2 * 2 + 1], al[mt], bh + 2);
                }
            }
        }
        __syncthreads();
    }

    const int g = lane >> 2, tg = lane & 3;
#pragma unroll
    for (int mt = 0; mt < 2; mt++)
#pragma unroll
        for (int h = 0; h < 2; h++) {
            int rl = wr * 32 + mt * 16 + h * 8 + g;
            float* crow = Cout + (m0 + rl) * Hv + n0g + wc * 64 + tg * 2;
#pragma unroll
            for (int nt = 0; nt < 8; nt++) {
                float2 v = {acc[mt][nt][2 * h], acc[mt][nt][2 * h + 1]};
                *(float2*)(crow + nt * 8) = v;
            }
        }
}

// ---------------- deterministic per-channel stats ----------------------------
template <int S>
__global__ void colstats() {
    const float* Y = (S == 1) ? g_y1 : g_y2;
    const int c = threadIdx.x;
    const float* p = Y + (size_t)blockIdx.x * 256 * Hv + c;
    float s = 0.f, q = 0.f;
#pragma unroll 8
    for (int r = 0; r < 256; r++) {
        float v = p[(size_t)r * Hv];
        s += v;
        q = fmaf(v, v, q);
    }
    g_psum[blockIdx.x * Hv + c] = s;
    g_psq[blockIdx.x * Hv + c] = q;
}

template <int S>
__global__ void colstats_finalize(const float* __restrict__ gamma,
                                  const float* __restrict__ beta) {
    const int c = threadIdx.x;
    float s = 0.f, q = 0.f;
    for (int i = 0; i < 256; i++) {
        s += g_psum[i * Hv + c];
        q += g_psq[i * Hv + c];
    }
    const float inv = 1.f / (float)NPTS;
    float mean = s * inv;
    float var = q * inv - mean * mean;
    float sc = gamma[c] * rsqrtf(var + 1e-5f);
    if (S == 1) { g_sc1[c] = sc; g_sh1[c] = beta[c] - mean * sc; }
    else        { g_sc2[c] = sc; g_sh2[c] = beta[c] - mean * sc; }
}

// ---------------- BN2 + ReLU + transpose to (B, H, N) ------------------------
__global__ void bn_transpose_out(float* __restrict__ out) {
    __shared__ float t[32][33];
    const int b = blockIdx.z;
    const int h0 = blockIdx.x * 32;
    const int n0 = blockIdx.y * 32;
    const int tx = threadIdx.x;
    float sc = g_sc2[h0 + tx], sh = g_sh2[h0 + tx];
#pragma unroll
    for (int i = threadIdx.y; i < 32; i += 8) {
        float v = g_y2[((size_t)(b * Nv + n0 + i)) * Hv + h0 + tx];
        t[i][tx] = fmaxf(fmaf(v, sc, sh), 0.f);
    }
    __syncthreads();
#pragma unroll
    for (int i = threadIdx.y; i < 32; i += 8)
        out[((size_t)(b * Hv + h0 + i)) * Nv + n0 + tx] = t[tx][i];
}

// ---------------- launcher ----------------------------------------------------
extern "C" void kernel_launch(void* const* d_in, const int* in_sizes, int n_in,
                              void* d_out, int out_size) {
    const float* unknown      = (const float*)d_in[0];
    const float* known        = (const float*)d_in[1];
    const float* unknow_feats = (const float*)d_in[2];
    const float* known_feats  = (const float*)d_in[3];
    const float* w1           = (const float*)d_in[4];
    const float* g1           = (const float*)d_in[5];
    const float* b1           = (const float*)d_in[6];
    const float* w2           = (const float*)d_in[7];
    const float* g2           = (const float*)d_in[8];
    const float* b2           = (const float*)d_in[9];
    float* out = (float*)d_out;

    const int SMEM_PIPE = 131072;        // 2 stages x 64KB
    const int SMEM_BN = 65536 + 2048;
    cudaFuncSetAttribute(mma_gemm_pipe<0>, cudaFuncAttributeMaxDynamicSharedMemorySize, SMEM_PIPE);
    cudaFuncSetAttribute(mma_gemm_pipe<1>, cudaFuncAttributeMaxDynamicSharedMemorySize, SMEM_PIPE);
    cudaFuncSetAttribute(mma_gemm_bn, cudaFuncAttributeMaxDynamicSharedMemorySize, SMEM_BN);

    dim3 tb(32, 8);

    conv_w1<<<768, 256>>>(w1);
    conv_w2<<<256, 256>>>(w2);
    knn_kernel<<<dim3(Bv, Nv / 256), 256>>>(unknown, known);
    conv_transpose<0><<<dim3(Mv / 32, C2v / 32, Bv), tb>>>(known_feats);
    conv_transpose<1><<<dim3(Nv / 32, C1v / 32, Bv), tb>>>(unknow_feats);

    // kfW = kf @ w1b^T  (pipelined)
    mma_gemm_pipe<0><<<dim3(KFROWS / 128, 2), 256, SMEM_PIPE>>>();
    // y1 = uf @ w1a^T + NN-gather epilogue  (pipelined)
    mma_gemm_pipe<1><<<dim3(NPTS / 128, 2), 256, SMEM_PIPE>>>();

    colstats<1><<<256, 256>>>();
    colstats_finalize<1><<<1, 256>>>(g1, b1);

    // y2 = relu(bn1(y1)) @ w2^T  (R6-exact single-buffer, 2 CTA/SM)
    mma_gemm_bn<<<dim3(NPTS / 128, 2), 256, SMEM_BN>>>();

    colstats<2><<<256, 256>>>();
    colstats_finalize<2><<<1, 256>>>(g2, b2);

    bn_transpose_out<<<dim3(Hv / 32, Nv / 32, Bv), tb>>>(out);
}

// round 16
// speedup vs baseline: 1.0039x; 1.0039x over previous
#include <cuda_runtime.h>
#include <cuda_bf16.h>
#include <cstdint>

// Problem constants
#define Bv   16
#define Nv   4096
#define Mv   1024
#define C1v  256
#define C2v  512
#define Hv   256
#define NPTS  (Bv * Nv)    // 65536
#define KFROWS (Bv * Mv)   // 16384

// ---------------- device-global scratch (no cudaMalloc allowed) -------------
static __device__ __nv_bfloat16 g_kf_hi[(size_t)KFROWS * C2v], g_kf_lo[(size_t)KFROWS * C2v];
static __device__ __nv_bfloat16 g_uf_hi[(size_t)NPTS * C1v],   g_uf_lo[(size_t)NPTS * C1v];
static __device__ __nv_bfloat16 g_w1a_hi[Hv * C1v], g_w1a_lo[Hv * C1v];
static __device__ __nv_bfloat16 g_w1b_hi[Hv * C2v], g_w1b_lo[Hv * C2v];
static __device__ __nv_bfloat16 g_w2_hi[Hv * Hv],   g_w2_lo[Hv * Hv];
static __device__ float g_kfW[(size_t)KFROWS * Hv];
static __device__ float g_y1[(size_t)NPTS * Hv];
static __device__ float g_y2[(size_t)NPTS * Hv];
static __device__ int4   g_nni[NPTS];
static __device__ float4 g_nnw[NPTS];
static __device__ float g_psum[256 * Hv], g_psq[256 * Hv];
static __device__ float g_sc1[Hv], g_sh1[Hv], g_sc2[Hv], g_sh2[Hv];

// ---------------- PTX helpers (baseline sm_80+, no 'a' features) ------------
__device__ __forceinline__ uint32_t smem_u32(const void* p) {
    uint32_t a;
    asm("{ .reg .u64 t; cvta.to.shared.u64 t, %1; cvt.u32.u64 %0, t; }" : "=r"(a) : "l"(p));
    return a;
}
__device__ __forceinline__ void cpasync16(uint32_t dst, const void* src) {
    size_t g = __cvta_generic_to_global(src);
    asm volatile("cp.async.cg.shared.global [%0], [%1], 16;" :: "r"(dst), "l"(g));
}
#define CP_COMMIT() asm volatile("cp.async.commit_group;" ::: "memory")
#define CP_WAIT0()  asm volatile("cp.async.wait_group 0;" ::: "memory")

__device__ __forceinline__ void ldsm4(uint32_t* r, uint32_t addr) {
    asm volatile("ldmatrix.sync.aligned.m8n8.x4.shared.b16 {%0,%1,%2,%3}, [%4];"
        : "=r"(r[0]), "=r"(r[1]), "=r"(r[2]), "=r"(r[3]) : "r"(addr));
}
__device__ __forceinline__ void mma16816(float* d, const uint32_t* a, const uint32_t* b) {
    asm volatile(
        "mma.sync.aligned.m16n8k16.row.col.f32.bf16.bf16.f32 "
        "{%0,%1,%2,%3}, {%4,%5,%6,%7}, {%8,%9}, {%0,%1,%2,%3};"
        : "+f"(d[0]), "+f"(d[1]), "+f"(d[2]), "+f"(d[3])
        : "r"(a[0]), "r"(a[1]), "r"(a[2]), "r"(a[3]), "r"(b[0]), "r"(b[1]));
}

// ---------------- bf16 split helpers ----------------------------------------
__device__ __forceinline__ void split_bf16(float v, __nv_bfloat16& h, __nv_bfloat16& l) {
    h = __float2bfloat16(v);
    l = __float2bfloat16(v - __bfloat162float(h));
}
__device__ __forceinline__ uint32_t pack2(__nv_bfloat16 a, __nv_bfloat16 b) {
    __nv_bfloat162 t(a, b);
    return *reinterpret_cast<uint32_t*>(&t);
}

// ---------------- weight split (w is already [N,K] K-major) -----------------
__global__ void conv_w1(const float* __restrict__ w1) {
    int i = blockIdx.x * 256 + threadIdx.x;   // 256*768
    int n = i / 768, k = i % 768;
    __nv_bfloat16 h, l;
    split_bf16(w1[i], h, l);
    if (k < C1v) { g_w1a_hi[n * C1v + k] = h; g_w1a_lo[n * C1v + k] = l; }
    else { g_w1b_hi[n * C2v + k - C1v] = h; g_w1b_lo[n * C2v + k - C1v] = l; }
}
__global__ void conv_w2(const float* __restrict__ w2) {
    int i = blockIdx.x * 256 + threadIdx.x;
    __nv_bfloat16 h, l;
    split_bf16(w2[i], h, l);
    g_w2_hi[i] = h; g_w2_lo[i] = l;
}

// ---------------- transpose + split: (B, C, Nper) -> (B*Nper, C) hi/lo ------
template <int WHICH>   // 0: kf (C=512, Nper=1024)  1: uf (C=256, Nper=4096)
__global__ void conv_transpose(const float* __restrict__ in) {
    constexpr int C = (WHICH == 0) ? C2v : C1v;
    constexpr int Nper = (WHICH == 0) ? Mv : Nv;
    __nv_bfloat16* hi = (WHICH == 0) ? g_kf_hi : g_uf_hi;
    __nv_bfloat16* lo = (WHICH == 0) ? g_kf_lo : g_uf_lo;
    __shared__ float t[32][33];
    const int b = blockIdx.z;
    const int n0 = blockIdx.x * 32, c0 = blockIdx.y * 32;
    const float* ib = in + ((size_t)b * C + c0) * Nper + n0;
#pragma unroll
    for (int i = threadIdx.y; i < 32; i += 8)
        t[i][threadIdx.x] = ib[(size_t)i * Nper + threadIdx.x];
    __syncthreads();
    size_t base = ((size_t)b * Nper + n0) * C + c0 + threadIdx.x;
#pragma unroll
    for (int i = threadIdx.y; i < 32; i += 8) {
        __nv_bfloat16 h, l;
        split_bf16(t[threadIdx.x][i], h, l);
        hi[base + (size_t)i * C] = h;
        lo[base + (size_t)i * C] = l;
    }
}

// ---------------- 3-NN ------------------------------------------------------
__global__ __launch_bounds__(256) void knn_kernel(
    const float* __restrict__ unknown, const float* __restrict__ known) {
    __shared__ float4 kn[Mv];
    const int b = blockIdx.x;
    const int tid = threadIdx.x;
    const float* kb = known + (long)b * Mv * 3;
    for (int m = tid; m < Mv; m += 256) {
        float x = kb[m * 3], y = kb[m * 3 + 1], z = kb[m * 3 + 2];
        kn[m] = make_float4(x, y, z, x * x + y * y + z * z);
    }
    __syncthreads();
    const int n = blockIdx.y * 256 + tid;
    const float* up = unknown + ((long)b * Nv + n) * 3;
    float ux = up[0], uy = up[1], uz = up[2];
    float un2 = ux * ux + uy * uy + uz * uz;
    float ax = -2.f * ux, ay = -2.f * uy, az = -2.f * uz;
    float d0 = 1e30f, d1 = 1e30f, d2 = 1e30f;
    int i0 = 0, i1 = 0, i2 = 0;
#pragma unroll 4
    for (int m = 0; m < Mv; m++) {
        float4 p = kn[m];
        float d = fmaf(ax, p.x, fmaf(ay, p.y, fmaf(az, p.z, p.w)));
        if (d < d2) {
            if (d < d1) {
                d2 = d1; i2 = i1;
                if (d < d0) { d1 = d0; i1 = i0; d0 = d; i0 = m; }
                else        { d1 = d;  i1 = m; }
            } else { d2 = d; i2 = m; }
        }
    }
    d0 += un2; d1 += un2; d2 += un2;
    float w0 = 1.f / (d0 + 1e-8f), w1 = 1.f / (d1 + 1e-8f), w2 = 1.f / (d2 + 1e-8f);
    float ws = 1.f / (w0 + w1 + w2);
    g_nni[(long)b * Nv + n] = make_int4(i0, i1, i2, 0);
    g_nnw[(long)b * Nv + n] = make_float4(w0 * ws, w1 * ws, w2 * ws, 0.f);
}

// ---------------- pipelined HMMA bf16x3 GEMM (MODE 0/1), 2-stage -------------
// MODE 0: kfW = kf @ w1b^T   (K=512)
// MODE 1: y1  = uf @ w1a^T + NN-gather epilogue (K=256)
// SMEM per stage (64KB): A_HI +0, A_LO +16K, B_HI +32K, B_LO +48K; 2 stages.
template <int MODE>
__global__ __launch_bounds__(256, 1) void mma_gemm_pipe() {
    constexpr int KTOT = (MODE == 0) ? C2v : Hv;
    constexpr int NCH = KTOT / 64;
    constexpr uint32_t A_HI = 0, A_LO = 16384, B_HI = 32768, B_LO = 49152;
    constexpr uint32_t STAGE = 65536;

    extern __shared__ char smem[];
    const uint32_t sb = smem_u32(smem);

    const __nv_bfloat16* Ahi = (MODE == 0) ? g_kf_hi : g_uf_hi;
    const __nv_bfloat16* Alo = (MODE == 0) ? g_kf_lo : g_uf_lo;
    const __nv_bfloat16* Bhi = (MODE == 0) ? g_w1b_hi : g_w1a_hi;
    const __nv_bfloat16* Blo = (MODE == 0) ? g_w1b_lo : g_w1a_lo;
    float* Cout = (MODE == 0) ? g_kfW : g_y1;

    const int tid = threadIdx.x;
    const int lane = tid & 31, wid = tid >> 5;
    const int wr = wid & 3, wc = wid >> 2;        // warp grid 4(m) x 2(n)
    const long m0 = (long)blockIdx.x * 128;
    const int n0g = blockIdx.y * 128;

    float acc[2][8][4];
#pragma unroll
    for (int i = 0; i < 2; i++)
#pragma unroll
        for (int j = 0; j < 8; j++)
#pragma unroll
            for (int k = 0; k < 4; k++) acc[i][j][k] = 0.f;

    const int a_r = lane & 15;
    const int a_co = lane >> 4;
    const int b_r = (lane & 7) + ((lane >> 4) << 3);
    const int b_co = (lane >> 3) & 1;

    // loader thread mapping
    const int lr = tid >> 3, lc = tid & 7;
    const uint32_t lsw = lr * 128 + (((uint32_t)(lc ^ (lr & 7))) << 4);

    // ---- prologue: load chunk 0 into stage 0 ----
    {
        const int k0 = 0;
#pragma unroll
        for (int p = 0; p < 4; p++) {
            int r = lr + p * 32;
            uint32_t sw = lsw + p * 32 * 128;
            const size_t gia = (m0 + r) * (size_t)KTOT + k0 + lc * 8;
            cpasync16(sb + A_HI + sw, Ahi + gia);
            cpasync16(sb + A_LO + sw, Alo + gia);
            const size_t gib = (size_t)(n0g + r) * KTOT + k0 + lc * 8;
            cpasync16(sb + B_HI + sw, Bhi + gib);
            cpasync16(sb + B_LO + sw, Blo + gib);
        }
        CP_COMMIT();
    }

#pragma unroll 1
    for (int kc = 0; kc < NCH; kc++) {
        const uint32_t st = (kc & 1) * STAGE;
        CP_WAIT0();
        __syncthreads();
        // issue next chunk's loads into the other stage (overlaps compute below)
        if (kc + 1 < NCH) {
            const int k0 = (kc + 1) * 64;
            const uint32_t so = ((kc + 1) & 1) * STAGE;
#pragma unroll
            for (int p = 0; p < 4; p++) {
                int r = lr + p * 32;
                uint32_t sw = lsw + p * 32 * 128;
                const size_t gia = (m0 + r) * (size_t)KTOT + k0 + lc * 8;
                cpasync16(sb + so + A_HI + sw, Ahi + gia);
                cpasync16(sb + so + A_LO + sw, Alo + gia);
                const size_t gib = (size_t)(n0g + r) * KTOT + k0 + lc * 8;
                cpasync16(sb + so + B_HI + sw, Bhi + gib);
                cpasync16(sb + so + B_LO + sw, Blo + gib);
            }
            CP_COMMIT();
        }

        // ---- compute 4 k16 steps on stage st ----
#pragma unroll 1
        for (int kk = 0; kk < 4; kk++) {
            uint32_t ah[2][4], al[2][4];
#pragma unroll
            for (int mt = 0; mt < 2; mt++) {
                int row = wr * 32 + mt * 16 + a_r;
                uint32_t ac = (uint32_t)((2 * kk + a_co) ^ (row & 7));
                uint32_t ad = sb + st + A_HI + row * 128 + (ac << 4);
                ldsm4(ah[mt], ad);
                ldsm4(al[mt], ad + (A_LO - A_HI));
            }
#pragma unroll
            for (int nt2 = 0; nt2 < 4; nt2++) {
                int row = wc * 64 + nt2 * 16 + b_r;
                uint32_t bc = (uint32_t)((2 * kk + b_co) ^ (row & 7));
                uint32_t bd = sb + st + B_HI + row * 128 + (bc << 4);
                uint32_t bh[4], bl[4];
                ldsm4(bh, bd);
                ldsm4(bl, bd + (B_LO - B_HI));
#pragma unroll
                for (int mt = 0; mt < 2; mt++) {
                    mma16816(acc[mt][nt2 * 2 + 0], ah[mt], bh + 0);
                    mma16816(acc[mt][nt2 * 2 + 0], ah[mt], bl + 0);
                    mma16816(acc[mt][nt2 * 2 + 0], al[mt], bh + 0);
                    mma16816(acc[mt][nt2 * 2 + 1], ah[mt], bh + 2);
                    mma16816(acc[mt][nt2 * 2 + 1], ah[mt], bl + 2);
                    mma16816(acc[mt][nt2 * 2 + 1], al[mt], bh + 2);
                }
            }
        }
    }
    __syncthreads();

    // ---- epilogue ----
    int4* sidx = (int4*)smem;
    float4* swt = (float4*)(smem + 2048);
    int bIdx = 0;
    if (MODE == 1) {
        bIdx = (int)(m0 >> 12);
        if (tid < 128) {
            sidx[tid] = g_nni[m0 + tid];
            swt[tid] = g_nnw[m0 + tid];
        }
        __syncthreads();
    }
    const float* kfb = g_kfW + (size_t)bIdx * Mv * Hv;
    const int g = lane >> 2, tg = lane & 3;
#pragma unroll
    for (int mt = 0; mt < 2; mt++) {
#pragma unroll
        for (int h = 0; h < 2; h++) {
            int rl = wr * 32 + mt * 16 + h * 8 + g;
            long grow = m0 + rl;
            int4 id;
            float4 w;
            if (MODE == 1) { id = sidx[rl]; w = swt[rl]; }
            float* crow = Cout + grow * Hv + n0g + wc * 64 + tg * 2;
#pragma unroll
            for (int nt = 0; nt < 8; nt++) {
                float2 v = {acc[mt][nt][2 * h], acc[mt][nt][2 * h + 1]};
                if (MODE == 1) {
                    int col = n0g + wc * 64 + nt * 8 + tg * 2;
                    float2 f0 = *(const float2*)(kfb + (size_t)id.x * Hv + col);
                    float2 f1 = *(const float2*)(kfb + (size_t)id.y * Hv + col);
                    float2 f2 = *(const float2*)(kfb + (size_t)id.z * Hv + col);
                    v.x += w.x * f0.x + w.y * f1.x + w.z * f2.x;
                    v.y += w.x * f0.y + w.y * f1.y + w.z * f2.y;
                }
                *(float2*)(crow + nt * 8) = v;
            }
        }
    }
}

// ---------------- GEMM2 (R6-exact): y2 = relu(bn1(y1)) @ w2^T ----------------
__global__ __launch_bounds__(256, 2) void mma_gemm_bn() {
    constexpr int KTOT = Hv;
    constexpr int NCH = KTOT / 64;
    constexpr uint32_t A_HI = 0, A_LO = 16384, B_HI = 32768, B_LO = 49152;

    extern __shared__ char smem[];
    const uint32_t sb = smem_u32(smem);

    const __nv_bfloat16* Bhi = g_w2_hi;
    const __nv_bfloat16* Blo = g_w2_lo;
    float* Cout = g_y2;

    const int tid = threadIdx.x;
    const int lane = tid & 31, wid = tid >> 5;
    const int wr = wid & 3, wc = wid >> 2;
    const long m0 = (long)blockIdx.x * 128;
    const int n0g = blockIdx.y * 128;

    float* s_sc = (float*)(smem + 65536);
    float* s_sh = (float*)(smem + 65536 + 1024);
    if (tid < 64) {
        ((float4*)s_sc)[tid] = ((const float4*)g_sc1)[tid];
        ((float4*)s_sh)[tid] = ((const float4*)g_sh1)[tid];
    }
    __syncthreads();

    float acc[2][8][4];
#pragma unroll
    for (int i = 0; i < 2; i++)
#pragma unroll
        for (int j = 0; j < 8; j++)
#pragma unroll
            for (int k = 0; k < 4; k++) acc[i][j][k] = 0.f;

    const int a_r = lane & 15;
    const int a_co = lane >> 4;
    const int b_r = (lane & 7) + ((lane >> 4) << 3);
    const int b_co = (lane >> 3) & 1;

#pragma unroll 1
    for (int kc = 0; kc < NCH; kc++) {
        const int k0 = kc * 64;
        // A: BN+ReLU+split synchronous
#pragma unroll
        for (int p = 0; p < 4; p++) {
            int idx = p * 256 + tid;
            int r = idx >> 3, c = idx & 7;
            int kb = k0 + c * 8;
            const float* src = g_y1 + (m0 + r) * (size_t)Hv + kb;
            float4 x0 = *(const float4*)src;
            float4 x1 = *(const float4*)(src + 4);
            float v[8];
            v[0] = fmaxf(fmaf(x0.x, s_sc[kb + 0], s_sh[kb + 0]), 0.f);
            v[1] = fmaxf(fmaf(x0.y, s_sc[kb + 1], s_sh[kb + 1]), 0.f);
            v[2] = fmaxf(fmaf(x0.z, s_sc[kb + 2], s_sh[kb + 2]), 0.f);
            v[3] = fmaxf(fmaf(x0.w, s_sc[kb + 3], s_sh[kb + 3]), 0.f);
            v[4] = fmaxf(fmaf(x1.x, s_sc[kb + 4], s_sh[kb + 4]), 0.f);
            v[5] = fmaxf(fmaf(x1.y, s_sc[kb + 5], s_sh[kb + 5]), 0.f);
            v[6] = fmaxf(fmaf(x1.z, s_sc[kb + 6], s_sh[kb + 6]), 0.f);
            v[7] = fmaxf(fmaf(x1.w, s_sc[kb + 7], s_sh[kb + 7]), 0.f);
            uint4 hq, lq;
            uint32_t* hp = (uint32_t*)&hq;
            uint32_t* lp = (uint32_t*)&lq;
#pragma unroll
            for (int j = 0; j < 4; j++) {
                __nv_bfloat16 h0, l0, h1, l1;
                split_bf16(v[2 * j], h0, l0);
                split_bf16(v[2 * j + 1], h1, l1);
                hp[j] = pack2(h0, h1);
                lp[j] = pack2(l0, l1);
            }
            uint32_t sw = r * 128 + (((uint32_t)(c ^ (r & 7))) << 4);
            *(uint4*)(smem + A_HI + sw) = hq;
            *(uint4*)(smem + A_LO + sw) = lq;
        }
        // B: async
#pragma unroll
        for (int p = 0; p < 4; p++) {
            int idx = p * 256 + tid;
            int r = idx >> 3, c = idx & 7;
            uint32_t sw = r * 128 + (((uint32_t)(c ^ (r & 7))) << 4);
            const size_t gi = (size_t)(n0g + r) * KTOT + k0 + c * 8;
            cpasync16(sb + B_HI + sw, Bhi + gi);
            cpasync16(sb + B_LO + sw, Blo + gi);
        }
        CP_COMMIT();
        CP_WAIT0();
        __syncthreads();

#pragma unroll 1
        for (int kk = 0; kk < 4; kk++) {
            uint32_t ah[2][4], al[2][4];
#pragma unroll
            for (int mt = 0; mt < 2; mt++) {
                int row = wr * 32 + mt * 16 + a_r;
                uint32_t ac = (uint32_t)((2 * kk + a_co) ^ (row & 7));
                uint32_t ad = sb + A_HI + row * 128 + (ac << 4);
                ldsm4(ah[mt], ad);
                ldsm4(al[mt], ad + (A_LO - A_HI));
            }
#pragma unroll
            for (int nt2 = 0; nt2 < 4; nt2++) {
                int row = wc * 64 + nt2 * 16 + b_r;
                uint32_t bc = (uint32_t)((2 * kk + b_co) ^ (row & 7));
                uint32_t bd = sb + B_HI + row * 128 + (bc << 4);
                uint32_t bh[4], bl[4];
                ldsm4(bh, bd);
                ldsm4(bl, bd + (B_LO - B_HI));
#pragma unroll
                for (int mt = 0; mt < 2; mt++) {
                    mma16816(acc[mt][nt2 * 2 + 0], ah[mt], bh + 0);
                    mma16816(acc[mt][nt2 * 2 + 0], ah[mt], bl + 0);
                    mma16816(acc[mt][nt2 * 2 + 0], al[mt], bh + 0);
                    mma16816(acc[mt][nt2 * 2 + 1], ah[mt], bh + 2);
                    mma16816(acc[mt][nt2 * 2 + 1], ah[mt], bl + 2);
                    mma16816(acc[mt][nt2 * 2 + 1], al[mt], bh + 2);
                }
            }
        }
        __syncthreads();
    }

    const int g = lane >> 2, tg = lane & 3;
#pragma unroll
    for (int mt = 0; mt < 2; mt++)
#pragma unroll
        for (int h = 0; h < 2; h++) {
            int rl = wr * 32 + mt * 16 + h * 8 + g;
            float* crow = Cout + (m0 + rl) * Hv + n0g + wc * 64 + tg * 2;
#pragma unroll
            for (int nt = 0; nt < 8; nt++) {
                float2 v = {acc[mt][nt][2 * h], acc[mt][nt][2 * h + 1]};
                *(float2*)(crow + nt * 8) = v;
            }
        }
}

// ---------------- deterministic per-channel stats ----------------------------
template <int S>
__global__ void colstats() {
    const float* Y = (S == 1) ? g_y1 : g_y2;
    const int c = threadIdx.x;
    const float* p = Y + (size_t)blockIdx.x * 256 * Hv + c;
    float s = 0.f, q = 0.f;
#pragma unroll 8
    for (int r = 0; r < 256; r++) {
        float v = p[(size_t)r * Hv];
        s += v;
        q = fmaf(v, v, q);
    }
    g_psum[blockIdx.x * Hv + c] = s;
    g_psq[blockIdx.x * Hv + c] = q;
}

template <int S>
__global__ void colstats_finalize(const float* __restrict__ gamma,
                                  const float* __restrict__ beta) {
    const int c = threadIdx.x;
    float s = 0.f, q = 0.f;
    for (int i = 0; i < 256; i++) {
        s += g_psum[i * Hv + c];
        q += g_psq[i * Hv + c];
    }
    const float inv = 1.f / (float)NPTS;
    float mean = s * inv;
    float var = q * inv - mean * mean;
    float sc = gamma[c] * rsqrtf(var + 1e-5f);
    if (S == 1) { g_sc1[c] = sc; g_sh1[c] = beta[c] - mean * sc; }
    else        { g_sc2[c] = sc; g_sh2[c] = beta[c] - mean * sc; }
}

// ---------------- BN2 + ReLU + transpose to (B, H, N) ------------------------
__global__ void bn_transpose_out(float* __restrict__ out) {
    __shared__ float t[32][33];
    const int b = blockIdx.z;
    const int h0 = blockIdx.x * 32;
    const int n0 = blockIdx.y * 32;
    const int tx = threadIdx.x;
    float sc = g_sc2[h0 + tx], sh = g_sh2[h0 + tx];
#pragma unroll
    for (int i = threadIdx.y; i < 32; i += 8) {
        float v = g_y2[((size_t)(b * Nv + n0 + i)) * Hv + h0 + tx];
        t[i][tx] = fmaxf(fmaf(v, sc, sh), 0.f);
    }
    __syncthreads();
#pragma unroll
    for (int i = threadIdx.y; i < 32; i += 8)
        out[((size_t)(b * Hv + h0 + i)) * Nv + n0 + tx] = t[tx][i];
}

// ---------------- launcher ----------------------------------------------------
extern "C" void kernel_launch(void* const* d_in, const int* in_sizes, int n_in,
                              void* d_out, int out_size) {
    const float* unknown      = (const float*)d_in[0];
    const float* known        = (const float*)d_in[1];
    const float* unknow_feats = (const float*)d_in[2];
    const float* known_feats  = (const float*)d_in[3];
    const float* w1           = (const float*)d_in[4];
    const float* g1           = (const float*)d_in[5];
    const float* b1           = (const float*)d_in[6];
    const float* w2           = (const float*)d_in[7];
    const float* g2           = (const float*)d_in[8];
    const float* b2           = (const float*)d_in[9];
    float* out = (float*)d_out;

    const int SMEM_PIPE = 131072;        // 2 stages x 64KB
    const int SMEM_BN = 65536 + 2048;
    cudaFuncSetAttribute(mma_gemm_pipe<0>, cudaFuncAttributeMaxDynamicSharedMemorySize, SMEM_PIPE);
    cudaFuncSetAttribute(mma_gemm_pipe<1>, cudaFuncAttributeMaxDynamicSharedMemorySize, SMEM_PIPE);
    cudaFuncSetAttribute(mma_gemm_bn, cudaFuncAttributeMaxDynamicSharedMemorySize, SMEM_BN);

    dim3 tb(32, 8);

    conv_w1<<<768, 256>>>(w1);
    conv_w2<<<256, 256>>>(w2);
    knn_kernel<<<dim3(Bv, Nv / 256), 256>>>(unknown, known);
    conv_transpose<0><<<dim3(Mv / 32, C2v / 32, Bv), tb>>>(known_feats);
    conv_transpose<1><<<dim3(Nv / 32, C1v / 32, Bv), tb>>>(unknow_feats);

    // kfW = kf @ w1b^T  (pipelined)
    mma_gemm_pipe<0><<<dim3(KFROWS / 128, 2), 256, SMEM_PIPE>>>();
    // y1 = uf @ w1a^T + NN-gather epilogue  (pipelined)
    mma_gemm_pipe<1><<<dim3(NPTS / 128, 2), 256, SMEM_PIPE>>>();

    colstats<1><<<256, 256>>>();
    colstats_finalize<1><<<1, 256>>>(g1, b1);

    // y2 = relu(bn1(y1)) @ w2^T  (R6-exact single-buffer, 2 CTA/SM)
    mma_gemm_bn<<<dim3(NPTS / 128, 2), 256, SMEM_BN>>>();

    colstats<2><<<256, 256>>>();
    colstats_finalize<2><<<1, 256>>>(g2, b2);

    bn_transpose_out<<<dim3(Hv / 32, Nv / 32, Bv), tb>>>(out);
}

// round 17
// speedup vs baseline: 1.0048x; 1.0009x over previous
#include <cuda_runtime.h>
#include <cuda_bf16.h>
#include <cstdint>

// Problem constants
#define Bv   16
#define Nv   4096
#define Mv   1024
#define C1v  256
#define C2v  512
#define Hv   256
#define NPTS  (Bv * Nv)    // 65536
#define KFROWS (Bv * Mv)   // 16384

// ---------------- device-global scratch (no cudaMalloc allowed) -------------
static __device__ __nv_bfloat16 g_kf_hi[(size_t)KFROWS * C2v], g_kf_lo[(size_t)KFROWS * C2v];
static __device__ __nv_bfloat16 g_uf_hi[(size_t)NPTS * C1v],   g_uf_lo[(size_t)NPTS * C1v];
static __device__ __nv_bfloat16 g_w1a_hi[Hv * C1v], g_w1a_lo[Hv * C1v];
static __device__ __nv_bfloat16 g_w1b_hi[Hv * C2v], g_w1b_lo[Hv * C2v];
static __device__ __nv_bfloat16 g_w2_hi[Hv * Hv],   g_w2_lo[Hv * Hv];
static __device__ float g_kfW[(size_t)KFROWS * Hv];
static __device__ float g_y1[(size_t)NPTS * Hv];
static __device__ float g_y2[(size_t)NPTS * Hv];
static __device__ int4   g_nni[NPTS];
static __device__ float4 g_nnw[NPTS];
static __device__ float g_psum[256 * Hv], g_psq[256 * Hv];
static __device__ float g_sc1[Hv], g_sh1[Hv], g_sc2[Hv], g_sh2[Hv];

// ---------------- PTX helpers (baseline sm_80+, no 'a' features) ------------
__device__ __forceinline__ uint32_t smem_u32(const void* p) {
    uint32_t a;
    asm("{ .reg .u64 t; cvta.to.shared.u64 t, %1; cvt.u32.u64 %0, t; }" : "=r"(a) : "l"(p));
    return a;
}
__device__ __forceinline__ void cpasync16(uint32_t dst, const void* src) {
    size_t g = __cvta_generic_to_global(src);
    asm volatile("cp.async.cg.shared.global [%0], [%1], 16;" :: "r"(dst), "l"(g));
}
#define CP_COMMIT() asm volatile("cp.async.commit_group;" ::: "memory")
#define CP_WAIT0()  asm volatile("cp.async.wait_group 0;" ::: "memory")

__device__ __forceinline__ void ldsm4(uint32_t* r, uint32_t addr) {
    asm volatile("ldmatrix.sync.aligned.m8n8.x4.shared.b16 {%0,%1,%2,%3}, [%4];"
        : "=r"(r[0]), "=r"(r[1]), "=r"(r[2]), "=r"(r[3]) : "r"(addr));
}
__device__ __forceinline__ void mma16816(float* d, const uint32_t* a, const uint32_t* b) {
    asm volatile(
        "mma.sync.aligned.m16n8k16.row.col.f32.bf16.bf16.f32 "
        "{%0,%1,%2,%3}, {%4,%5,%6,%7}, {%8,%9}, {%0,%1,%2,%3};"
        : "+f"(d[0]), "+f"(d[1]), "+f"(d[2]), "+f"(d[3])
        : "r"(a[0]), "r"(a[1]), "r"(a[2]), "r"(a[3]), "r"(b[0]), "r"(b[1]));
}

// ---------------- bf16 split helpers ----------------------------------------
__device__ __forceinline__ void split_bf16(float v, __nv_bfloat16& h, __nv_bfloat16& l) {
    h = __float2bfloat16(v);
    l = __float2bfloat16(v - __bfloat162float(h));
}
__device__ __forceinline__ uint32_t pack2(__nv_bfloat16 a, __nv_bfloat16 b) {
    __nv_bfloat162 t(a, b);
    return *reinterpret_cast<uint32_t*>(&t);
}

// ---------------- weight split (w is already [N,K] K-major) -----------------
__global__ void conv_w1(const float* __restrict__ w1) {
    int i = blockIdx.x * 256 + threadIdx.x;   // 256*768
    int n = i / 768, k = i % 768;
    __nv_bfloat16 h, l;
    split_bf16(w1[i], h, l);
    if (k < C1v) { g_w1a_hi[n * C1v + k] = h; g_w1a_lo[n * C1v + k] = l; }
    else { g_w1b_hi[n * C2v + k - C1v] = h; g_w1b_lo[n * C2v + k - C1v] = l; }
}
__global__ void conv_w2(const float* __restrict__ w2) {
    int i = blockIdx.x * 256 + threadIdx.x;
    __nv_bfloat16 h, l;
    split_bf16(w2[i], h, l);
    g_w2_hi[i] = h; g_w2_lo[i] = l;
}

// ---------------- transpose + split: (B, C, Nper) -> (B*Nper, C) hi/lo ------
template <int WHICH>   // 0: kf (C=512, Nper=1024)  1: uf (C=256, Nper=4096)
__global__ void conv_transpose(const float* __restrict__ in) {
    constexpr int C = (WHICH == 0) ? C2v : C1v;
    constexpr int Nper = (WHICH == 0) ? Mv : Nv;
    __nv_bfloat16* hi = (WHICH == 0) ? g_kf_hi : g_uf_hi;
    __nv_bfloat16* lo = (WHICH == 0) ? g_kf_lo : g_uf_lo;
    __shared__ float t[32][33];
    const int b = blockIdx.z;
    const int n0 = blockIdx.x * 32, c0 = blockIdx.y * 32;
    const float* ib = in + ((size_t)b * C + c0) * Nper + n0;
#pragma unroll
    for (int i = threadIdx.y; i < 32; i += 8)
        t[i][threadIdx.x] = ib[(size_t)i * Nper + threadIdx.x];
    __syncthreads();
    size_t base = ((size_t)b * Nper + n0) * C + c0 + threadIdx.x;
#pragma unroll
    for (int i = threadIdx.y; i < 32; i += 8) {
        __nv_bfloat16 h, l;
        split_bf16(t[threadIdx.x][i], h, l);
        hi[base + (size_t)i * C] = h;
        lo[base + (size_t)i * C] = l;
    }
}

// ---------------- 3-NN ------------------------------------------------------
__global__ __launch_bounds__(256) void knn_kernel(
    const float* __restrict__ unknown, const float* __restrict__ known) {
    __shared__ float4 kn[Mv];
    const int b = blockIdx.x;
    const int tid = threadIdx.x;
    const float* kb = known + (long)b * Mv * 3;
    for (int m = tid; m < Mv; m += 256) {
        float x = kb[m * 3], y = kb[m * 3 + 1], z = kb[m * 3 + 2];
        kn[m] = make_float4(x, y, z, x * x + y * y + z * z);
    }
    __syncthreads();
    const int n = blockIdx.y * 256 + tid;
    const float* up = unknown + ((long)b * Nv + n) * 3;
    float ux = up[0], uy = up[1], uz = up[2];
    float un2 = ux * ux + uy * uy + uz * uz;
    float ax = -2.f * ux, ay = -2.f * uy, az = -2.f * uz;
    float d0 = 1e30f, d1 = 1e30f, d2 = 1e30f;
    int i0 = 0, i1 = 0, i2 = 0;
#pragma unroll 4
    for (int m = 0; m < Mv; m++) {
        float4 p = kn[m];
        float d = fmaf(ax, p.x, fmaf(ay, p.y, fmaf(az, p.z, p.w)));
        if (d < d2) {
            if (d < d1) {
                d2 = d1; i2 = i1;
                if (d < d0) { d1 = d0; i1 = i0; d0 = d; i0 = m; }
                else        { d1 = d;  i1 = m; }
            } else { d2 = d; i2 = m; }
        }
    }
    d0 += un2; d1 += un2; d2 += un2;
    float w0 = 1.f / (d0 + 1e-8f), w1 = 1.f / (d1 + 1e-8f), w2 = 1.f / (d2 + 1e-8f);
    float ws = 1.f / (w0 + w1 + w2);
    g_nni[(long)b * Nv + n] = make_int4(i0, i1, i2, 0);
    g_nnw[(long)b * Nv + n] = make_float4(w0 * ws, w1 * ws, w2 * ws, 0.f);
}

// ---------------- pipelined HMMA bf16x3 GEMM (MODE 0/1), 2-stage -------------
// MODE 0: kfW = kf @ w1b^T   (K=512)
// MODE 1: y1  = uf @ w1a^T + NN-gather epilogue (K=256)
// SMEM per stage (64KB): A_HI +0, A_LO +16K, B_HI +32K, B_LO +48K; 2 stages.
template <int MODE>
__global__ __launch_bounds__(256, 1) void mma_gemm_pipe() {
    constexpr int KTOT = (MODE == 0) ? C2v : Hv;
    constexpr int NCH = KTOT / 64;
    constexpr uint32_t A_HI = 0, A_LO = 16384, B_HI = 32768, B_LO = 49152;
    constexpr uint32_t STAGE = 65536;

    extern __shared__ char smem[];
    const uint32_t sb = smem_u32(smem);

    const __nv_bfloat16* Ahi = (MODE == 0) ? g_kf_hi : g_uf_hi;
    const __nv_bfloat16* Alo = (MODE == 0) ? g_kf_lo : g_uf_lo;
    const __nv_bfloat16* Bhi = (MODE == 0) ? g_w1b_hi : g_w1a_hi;
    const __nv_bfloat16* Blo = (MODE == 0) ? g_w1b_lo : g_w1a_lo;
    float* Cout = (MODE == 0) ? g_kfW : g_y1;

    const int tid = threadIdx.x;
    const int lane = tid & 31, wid = tid >> 5;
    const int wr = wid & 3, wc = wid >> 2;        // warp grid 4(m) x 2(n)
    const long m0 = (long)blockIdx.x * 128;
    const int n0g = blockIdx.y * 128;

    float acc[2][8][4];
#pragma unroll
    for (int i = 0; i < 2; i++)
#pragma unroll
        for (int j = 0; j < 8; j++)
#pragma unroll
            for (int k = 0; k < 4; k++) acc[i][j][k] = 0.f;

    const int a_r = lane & 15;
    const int a_co = lane >> 4;
    const int b_r = (lane & 7) + ((lane >> 4) << 3);
    const int b_co = (lane >> 3) & 1;

    // loader thread mapping
    const int lr = tid >> 3, lc = tid & 7;
    const uint32_t lsw = lr * 128 + (((uint32_t)(lc ^ (lr & 7))) << 4);

    // ---- prologue: load chunk 0 into stage 0 ----
    {
        const int k0 = 0;
#pragma unroll
        for (int p = 0; p < 4; p++) {
            int r = lr + p * 32;
            uint32_t sw = lsw + p * 32 * 128;
            const size_t gia = (m0 + r) * (size_t)KTOT + k0 + lc * 8;
            cpasync16(sb + A_HI + sw, Ahi + gia);
            cpasync16(sb + A_LO + sw, Alo + gia);
            const size_t gib = (size_t)(n0g + r) * KTOT + k0 + lc * 8;
            cpasync16(sb + B_HI + sw, Bhi + gib);
            cpasync16(sb + B_LO + sw, Blo + gib);
        }
        CP_COMMIT();
    }

#pragma unroll 1
    for (int kc = 0; kc < NCH; kc++) {
        const uint32_t st = (kc & 1) * STAGE;
        CP_WAIT0();
        __syncthreads();
        // issue next chunk's loads into the other stage (overlaps compute below)
        if (kc + 1 < NCH) {
            const int k0 = (kc + 1) * 64;
            const uint32_t so = ((kc + 1) & 1) * STAGE;
#pragma unroll
            for (int p = 0; p < 4; p++) {
                int r = lr + p * 32;
                uint32_t sw = lsw + p * 32 * 128;
                const size_t gia = (m0 + r) * (size_t)KTOT + k0 + lc * 8;
                cpasync16(sb + so + A_HI + sw, Ahi + gia);
                cpasync16(sb + so + A_LO + sw, Alo + gia);
                const size_t gib = (size_t)(n0g + r) * KTOT + k0 + lc * 8;
                cpasync16(sb + so + B_HI + sw, Bhi + gib);
                cpasync16(sb + so + B_LO + sw, Blo + gib);
            }
            CP_COMMIT();
        }

        // ---- compute 4 k16 steps on stage st ----
#pragma unroll 1
        for (int kk = 0; kk < 4; kk++) {
            uint32_t ah[2][4], al[2][4];
#pragma unroll
            for (int mt = 0; mt < 2; mt++) {
                int row = wr * 32 + mt * 16 + a_r;
                uint32_t ac = (uint32_t)((2 * kk + a_co) ^ (row & 7));
                uint32_t ad = sb + st + A_HI + row * 128 + (ac << 4);
                ldsm4(ah[mt], ad);
                ldsm4(al[mt], ad + (A_LO - A_HI));
            }
#pragma unroll
            for (int nt2 = 0; nt2 < 4; nt2++) {
                int row = wc * 64 + nt2 * 16 + b_r;
                uint32_t bc = (uint32_t)((2 * kk + b_co) ^ (row & 7));
                uint32_t bd = sb + st + B_HI + row * 128 + (bc << 4);
                uint32_t bh[4], bl[4];
                ldsm4(bh, bd);
                ldsm4(bl, bd + (B_LO - B_HI));
#pragma unroll
                for (int mt = 0; mt < 2; mt++) {
                    mma16816(acc[mt][nt2 * 2 + 0], ah[mt], bh + 0);
                    mma16816(acc[mt][nt2 * 2 + 0], ah[mt], bl + 0);
                    mma16816(acc[mt][nt2 * 2 + 0], al[mt], bh + 0);
                    mma16816(acc[mt][nt2 * 2 + 1], ah[mt], bh + 2);
                    mma16816(acc[mt][nt2 * 2 + 1], ah[mt], bl + 2);
                    mma16816(acc[mt][nt2 * 2 + 1], al[mt], bh + 2);
                }
            }
        }
    }
    __syncthreads();

    // ---- epilogue ----
    int4* sidx = (int4*)smem;
    float4* swt = (float4*)(smem + 2048);
    int bIdx = 0;
    if (MODE == 1) {
        bIdx = (int)(m0 >> 12);
        if (tid < 128) {
            sidx[tid] = g_nni[m0 + tid];
            swt[tid] = g_nnw[m0 + tid];
        }
        __syncthreads();
    }
    const float* kfb = g_kfW + (size_t)bIdx * Mv * Hv;
    const int g = lane >> 2, tg = lane & 3;
#pragma unroll
    for (int mt = 0; mt < 2; mt++) {
#pragma unroll
        for (int h = 0; h < 2; h++) {
            int rl = wr * 32 + mt * 16 + h * 8 + g;
            long grow = m0 + rl;
            int4 id;
            float4 w;
            if (MODE == 1) { id = sidx[rl]; w = swt[rl]; }
            float* crow = Cout + grow * Hv + n0g + wc * 64 + tg * 2;
#pragma unroll
            for (int nt = 0; nt < 8; nt++) {
                float2 v = {acc[mt][nt][2 * h], acc[mt][nt][2 * h + 1]};
                if (MODE == 1) {
                    int col = n0g + wc * 64 + nt * 8 + tg * 2;
                    float2 f0 = *(const float2*)(kfb + (size_t)id.x * Hv + col);
                    float2 f1 = *(const float2*)(kfb + (size_t)id.y * Hv + col);
                    float2 f2 = *(const float2*)(kfb + (size_t)id.z * Hv + col);
                    v.x += w.x * f0.x + w.y * f1.x + w.z * f2.x;
                    v.y += w.x * f0.y + w.y * f1.y + w.z * f2.y;
                }
                *(float2*)(crow + nt * 8) = v;
            }
        }
    }
}

// ---------------- GEMM2 (R6-exact): y2 = relu(bn1(y1)) @ w2^T ----------------
__global__ __launch_bounds__(256, 2) void mma_gemm_bn() {
    constexpr int KTOT = Hv;
    constexpr int NCH = KTOT / 64;
    constexpr uint32_t A_HI = 0, A_LO = 16384, B_HI = 32768, B_LO = 49152;

    extern __shared__ char smem[];
    const uint32_t sb = smem_u32(smem);

    const __nv_bfloat16* Bhi = g_w2_hi;
    const __nv_bfloat16* Blo = g_w2_lo;
    float* Cout = g_y2;

    const int tid = threadIdx.x;
    const int lane = tid & 31, wid = tid >> 5;
    const int wr = wid & 3, wc = wid >> 2;
    const long m0 = (long)blockIdx.x * 128;
    const int n0g = blockIdx.y * 128;

    float* s_sc = (float*)(smem + 65536);
    float* s_sh = (float*)(smem + 65536 + 1024);
    if (tid < 64) {
        ((float4*)s_sc)[tid] = ((const float4*)g_sc1)[tid];
        ((float4*)s_sh)[tid] = ((const float4*)g_sh1)[tid];
    }
    __syncthreads();

    float acc[2][8][4];
#pragma unroll
    for (int i = 0; i < 2; i++)
#pragma unroll
        for (int j = 0; j < 8; j++)
#pragma unroll
            for (int k = 0; k < 4; k++) acc[i][j][k] = 0.f;

    const int a_r = lane & 15;
    const int a_co = lane >> 4;
    const int b_r = (lane & 7) + ((lane >> 4) << 3);
    const int b_co = (lane >> 3) & 1;

#pragma unroll 1
    for (int kc = 0; kc < NCH; kc++) {
        const int k0 = kc * 64;
        // A: BN+ReLU+split synchronous
#pragma unroll
        for (int p = 0; p < 4; p++) {
            int idx = p * 256 + tid;
            int r = idx >> 3, c = idx & 7;
            int kb = k0 + c * 8;
            const float* src = g_y1 + (m0 + r) * (size_t)Hv + kb;
            float4 x0 = *(const float4*)src;
            float4 x1 = *(const float4*)(src + 4);
            float v[8];
            v[0] = fmaxf(fmaf(x0.x, s_sc[kb + 0], s_sh[kb + 0]), 0.f);
            v[1] = fmaxf(fmaf(x0.y, s_sc[kb + 1], s_sh[kb + 1]), 0.f);
            v[2] = fmaxf(fmaf(x0.z, s_sc[kb + 2], s_sh[kb + 2]), 0.f);
            v[3] = fmaxf(fmaf(x0.w, s_sc[kb + 3], s_sh[kb + 3]), 0.f);
            v[4] = fmaxf(fmaf(x1.x, s_sc[kb + 4], s_sh[kb + 4]), 0.f);
            v[5] = fmaxf(fmaf(x1.y, s_sc[kb + 5], s_sh[kb + 5]), 0.f);
            v[6] = fmaxf(fmaf(x1.z, s_sc[kb + 6], s_sh[kb + 6]), 0.f);
            v[7] = fmaxf(fmaf(x1.w, s_sc[kb + 7], s_sh[kb + 7]), 0.f);
            uint4 hq, lq;
            uint32_t* hp = (uint32_t*)&hq;
            uint32_t* lp = (uint32_t*)&lq;
#pragma unroll
            for (int j = 0; j < 4; j++) {
                __nv_bfloat16 h0, l0, h1, l1;
                split_bf16(v[2 * j], h0, l0);
                split_bf16(v[2 * j + 1], h1, l1);
                hp[j] = pack2(h0, h1);
                lp[j] = pack2(l0, l1);
            }
            uint32_t sw = r * 128 + (((uint32_t)(c ^ (r & 7))) << 4);
            *(uint4*)(smem + A_HI + sw) = hq;
            *(uint4*)(smem + A_LO + sw) = lq;
        }
        // B: async
#pragma unroll
        for (int p = 0; p < 4; p++) {
            int idx = p * 256 + tid;
            int r = idx >> 3, c = idx & 7;
            uint32_t sw = r * 128 + (((uint32_t)(c ^ (r & 7))) << 4);
            const size_t gi = (size_t)(n0g + r) * KTOT + k0 + c * 8;
            cpasync16(sb + B_HI + sw, Bhi + gi);
            cpasync16(sb + B_LO + sw, Blo + gi);
        }
        CP_COMMIT();
        CP_WAIT0();
        __syncthreads();

#pragma unroll 1
        for (int kk = 0; kk < 4; kk++) {
            uint32_t ah[2][4], al[2][4];
#pragma unroll
            for (int mt = 0; mt < 2; mt++) {
                int row = wr * 32 + mt * 16 + a_r;
                uint32_t ac = (uint32_t)((2 * kk + a_co) ^ (row & 7));
                uint32_t ad = sb + A_HI + row * 128 + (ac << 4);
                ldsm4(ah[mt], ad);
                ldsm4(al[mt], ad + (A_LO - A_HI));
            }
#pragma unroll
            for (int nt2 = 0; nt2 < 4; nt2++) {
                int row = wc * 64 + nt2 * 16 + b_r;
                uint32_t bc = (uint32_t)((2 * kk + b_co) ^ (row & 7));
                uint32_t bd = sb + B_HI + row * 128 + (bc << 4);
                uint32_t bh[4], bl[4];
                ldsm4(bh, bd);
                ldsm4(bl, bd + (B_LO - B_HI));
#pragma unroll
                for (int mt = 0; mt < 2; mt++) {
                    mma16816(acc[mt][nt2 * 2 + 0], ah[mt], bh + 0);
                    mma16816(acc[mt][nt2 * 2 + 0], ah[mt], bl + 0);
                    mma16816(acc[mt][nt2 * 2 + 0], al[mt], bh + 0);
                    mma16816(acc[mt][nt2 * 2 + 1], ah[mt], bh + 2);
                    mma16816(acc[mt][nt2 * 2 + 1], ah[mt], bl + 2);
                    mma16816(acc[mt][nt2 * 2 + 1], al[mt], bh + 2);
                }
            }
        }
        __syncthreads();
    }

    const int g = lane >> 2, tg = lane & 3;
#pragma unroll
    for (int mt = 0; mt < 2; mt++)
#pragma unroll
        for (int h = 0; h < 2; h++) {
            int rl = wr * 32 + mt * 16 + h * 8 + g;
            float* crow = Cout + (m0 + rl) * Hv + n0g + wc * 64 + tg * 2;
#pragma unroll
            for (int nt = 0; nt < 8; nt++) {
                float2 v = {acc[mt][nt][2 * h], acc[mt][nt][2 * h + 1]};
                *(float2*)(crow + nt * 8) = v;
            }
        }
}

// ---------------- deterministic per-channel stats ----------------------------
template <int S>
__global__ void colstats() {
    const float* Y = (S == 1) ? g_y1 : g_y2;
    const int c = threadIdx.x;
    const float* p = Y + (size_t)blockIdx.x * 256 * Hv + c;
    float s = 0.f, q = 0.f;
#pragma unroll 8
    for (int r = 0; r < 256; r++) {
        float v = p[(size_t)r * Hv];
        s += v;
        q = fmaf(v, v, q);
    }
    g_psum[blockIdx.x * Hv + c] = s;
    g_psq[blockIdx.x * Hv + c] = q;
}

template <int S>
__global__ void colstats_finalize(const float* __restrict__ gamma,
                                  const float* __restrict__ beta) {
    const int c = threadIdx.x;
    float s = 0.f, q = 0.f;
    for (int i = 0; i < 256; i++) {
        s += g_psum[i * Hv + c];
        q += g_psq[i * Hv + c];
    }
    const float inv = 1.f / (float)NPTS;
    float mean = s * inv;
    float var = q * inv - mean * mean;
    float sc = gamma[c] * rsqrtf(var + 1e-5f);
    if (S == 1) { g_sc1[c] = sc; g_sh1[c] = beta[c] - mean * sc; }
    else        { g_sc2[c] = sc; g_sh2[c] = beta[c] - mean * sc; }
}

// ---------------- BN2 + ReLU + transpose to (B, H, N) ------------------------
__global__ void bn_transpose_out(float* __restrict__ out) {
    __shared__ float t[32][33];
    const int b = blockIdx.z;
    const int h0 = blockIdx.x * 32;
    const int n0 = blockIdx.y * 32;
    const int tx = threadIdx.x;
    float sc = g_sc2[h0 + tx], sh = g_sh2[h0 + tx];
#pragma unroll
    for (int i = threadIdx.y; i < 32; i += 8) {
        float v = g_y2[((size_t)(b * Nv + n0 + i)) * Hv + h0 + tx];
        t[i][tx] = fmaxf(fmaf(v, sc, sh), 0.f);
    }
    __syncthreads();
#pragma unroll
    for (int i = threadIdx.y; i < 32; i += 8)
        out[((size_t)(b * Hv + h0 + i)) * Nv + n0 + tx] = t[tx][i];
}

// ---------------- launcher ----------------------------------------------------
extern "C" void kernel_launch(void* const* d_in, const int* in_sizes, int n_in,
                              void* d_out, int out_size) {
    const float* unknown      = (const float*)d_in[0];
    const float* known        = (const float*)d_in[1];
    const float* unknow_feats = (const float*)d_in[2];
    const float* known_feats  = (const float*)d_in[3];
    const float* w1           = (const float*)d_in[4];
    const float* g1           = (const float*)d_in[5];
    const float* b1           = (const float*)d_in[6];
    const float* w2           = (const float*)d_in[7];
    const float* g2           = (const float*)d_in[8];
    const float* b2           = (const float*)d_in[9];
    float* out = (float*)d_out;

    const int SMEM_PIPE = 131072;        // 2 stages x 64KB
    const int SMEM_BN = 65536 + 2048;
    cudaFuncSetAttribute(mma_gemm_pipe<0>, cudaFuncAttributeMaxDynamicSharedMemorySize, SMEM_PIPE);
    cudaFuncSetAttribute(mma_gemm_pipe<1>, cudaFuncAttributeMaxDynamicSharedMemorySize, SMEM_PIPE);
    cudaFuncSetAttribute(mma_gemm_bn, cudaFuncAttributeMaxDynamicSharedMemorySize, SMEM_BN);

    dim3 tb(32, 8);

    conv_w1<<<768, 256>>>(w1);
    conv_w2<<<256, 256>>>(w2);
    knn_kernel<<<dim3(Bv, Nv / 256), 256>>>(unknown, known);
    conv_transpose<0><<<dim3(Mv / 32, C2v / 32, Bv), tb>>>(known_feats);
    conv_transpose<1><<<dim3(Nv / 32, C1v / 32, Bv), tb>>>(unknow_feats);

    // kfW = kf @ w1b^T  (pipelined)
    mma_gemm_pipe<0><<<dim3(KFROWS / 128, 2), 256, SMEM_PIPE>>>();
    // y1 = uf @ w1a^T + NN-gather epilogue  (pipelined)
    mma_gemm_pipe<1><<<dim3(NPTS / 128, 2), 256, SMEM_PIPE>>>();

    colstats<1><<<256, 256>>>();
    colstats_finalize<1><<<1, 256>>>(g1, b1);

    // y2 = relu(bn1(y1)) @ w2^T  (R6-exact single-buffer, 2 CTA/SM)
    mma_gemm_bn<<<dim3(NPTS / 128, 2), 256, SMEM_BN>>>();

    colstats<2><<<256, 256>>>();
    colstats_finalize<2><<<1, 256>>>(g2, b2);

    bn_transpose_out<<<dim3(Hv / 32, Nv / 32, Bv), tb>>>(out);
}